// round 3
// baseline (speedup 1.0000x reference)
#include <cuda_runtime.h>

#define DIMC 192
#define RJ   48          // DIM / RED
#define BB   4
#define HH   256
#define WW   256
#define HWSZ (HH * WW)   // 65536
#define EPSV 1e-5f
#define SEGS 4           // segments per plane in pool
#define POOL_BLOCKS (DIMC * SEGS)   // 768 blocks per batch

// Scratch (device globals; no allocation allowed).
__device__ float        g_part[DIMC * SEGS];     // per-batch partial sums (batches serialize)
__device__ float        g_wt[BB * DIMC * 4];     // 4 surviving masked taps per (b,c)
__device__ unsigned int g_cnt = 0;               // wraps back to 0 every batch (replay-safe)

// ---------------------------------------------------------------------------
// Kernel 1 (per batch): segmented global-average pool + fused weight-gen tail.
// 768 blocks: block = (channel, segment). Last finishing block runs the MLP.
// ---------------------------------------------------------------------------
__global__ __launch_bounds__(256) void pool_wgen_kernel(
        const float* __restrict__ x, int b,
        const float* __restrict__ w1,
        const float* __restrict__ gamma,
        const float* __restrict__ beta,
        const float* __restrict__ rmean,
        const float* __restrict__ rvar,
        const float* __restrict__ w2,
        const float* __restrict__ b2) {
    const int c   = blockIdx.x >> 2;
    const int seg = blockIdx.x & 3;
    const int tid = threadIdx.x;

    // ---- segment reduction: 16384 floats = 4096 float4, 256 threads ----
    const float4* p = (const float4*)(x + ((size_t)(b * DIMC + c)) * HWSZ) + seg * (HWSZ / 4 / SEGS);
    float s = 0.f;
    #pragma unroll
    for (int i = 0; i < HWSZ / 4 / SEGS / 256; i++) {   // 16 iters
        float4 v = p[tid + i * 256];
        s += (v.x + v.y) + (v.z + v.w);
    }
    #pragma unroll
    for (int o = 16; o > 0; o >>= 1) s += __shfl_down_sync(0xffffffffu, s, o);
    __shared__ float sm[8];
    const int lane = tid & 31, wrp = tid >> 5;
    if (lane == 0) sm[wrp] = s;
    __syncthreads();
    __shared__ bool is_last;
    if (tid == 0) {
        float t = sm[0] + sm[1] + sm[2] + sm[3] + sm[4] + sm[5] + sm[6] + sm[7];
        g_part[c * SEGS + seg] = t;
        __threadfence();
        unsigned int old = atomicInc(&g_cnt, POOL_BLOCKS - 1);  // wraps 767 -> 0
        is_last = (old == POOL_BLOCKS - 1);
    }
    __syncthreads();
    if (!is_last) return;

    // ---- weight-gen tail (one block) ----
    __shared__ float pooled[DIMC];
    __shared__ float t48[RJ];
    if (tid < DIMC) {
        const float* gp = g_part + tid * SEGS;
        pooled[tid] = (gp[0] + gp[1] + gp[2] + gp[3]) * (1.0f / (float)HWSZ);
    }
    __syncthreads();
    if (tid < RJ) {
        const float* pw = w1 + tid * DIMC;
        float acc = 0.f;
        #pragma unroll 8
        for (int cc = 0; cc < DIMC; cc++) acc = fmaf(pooled[cc], pw[cc], acc);
        acc = gamma[tid] * (acc - rmean[tid]) * rsqrtf(rvar[tid] + EPSV) + beta[tid];
        t48[tid] = fmaxf(acc, 0.f);
    }
    __syncthreads();
    // 768 masked taps: mask 'A' keeps kernel positions 0..3 of the 3x3.
    #pragma unroll
    for (int i = 0; i < 3; i++) {
        const int idx = tid + i * 256;       // 0..767
        const int cc = idx >> 2;
        const int k  = idx & 3;
        const int o  = cc * 9 + k;
        const float* pw2 = w2 + (size_t)o * RJ;
        float acc = b2[o];
        #pragma unroll
        for (int j = 0; j < RJ; j++) acc = fmaf(t48[j], pw2[j], acc);
        g_wt[(b * DIMC + cc) * 4 + k] = acc;
    }
}

// ---------------------------------------------------------------------------
// Kernel 2 (per batch): masked depthwise conv. Active taps:
//   out(y,x) = w0*in(y-1,x-1) + w1*in(y-1,x) + w2*in(y-1,x+1) + w3*in(y,x-1) + bias
// Reads with __ldcs (batch data is L2-resident from pool; evict after use),
// writes with __stcs (streaming; don't pollute L2 for the next batch).
// ---------------------------------------------------------------------------
__global__ __launch_bounds__(512) void conv_kernel(const float* __restrict__ x,
                                                   const float* __restrict__ bias,
                                                   float* __restrict__ out, int b) {
    const int c  = blockIdx.y;               // 0..191
    const int bc = b * DIMC + c;
    const float4 wv = *(const float4*)(g_wt + bc * 4);
    const float w0 = wv.x, w1 = wv.y, w2 = wv.z, w3 = wv.w;
    const float bs = bias[c];

    const int tid = blockIdx.x * 512 + threadIdx.x;   // 0 .. HW/4-1
    const int xq = tid & 63;
    const int y  = tid >> 6;
    const int x0 = xq << 2;
    const int lane = threadIdx.x & 31;

    const float* base = x + (size_t)bc * HWSZ;
    const float* rowc = base + y * WW;
    const float* rowm = rowc - WW;

    const float4 bv = __ldcs((const float4*)(rowc + x0));

    float4 av;
    if (y > 0) {                              // warp-uniform
        av = __ldcs((const float4*)(rowm + x0));
    } else {
        av = make_float4(0.f, 0.f, 0.f, 0.f);
    }

    float am1 = __shfl_up_sync(0xffffffffu, av.w, 1);
    float bm1 = __shfl_up_sync(0xffffffffu, bv.w, 1);
    float ap4 = __shfl_down_sync(0xffffffffu, av.x, 1);

    if (lane == 0) {
        if (x0 > 0) {
            bm1 = rowc[x0 - 1];
            am1 = (y > 0) ? rowm[x0 - 1] : 0.f;
        } else {
            am1 = 0.f; bm1 = 0.f;
        }
    }
    if (lane == 31) {
        if (x0 + 4 < WW) {
            ap4 = (y > 0) ? rowm[x0 + 4] : 0.f;
        } else {
            ap4 = 0.f;
        }
    }

    float4 o;
    o.x = fmaf(w0, am1,  fmaf(w1, av.x, fmaf(w2, av.y, fmaf(w3, bm1,  bs))));
    o.y = fmaf(w0, av.x, fmaf(w1, av.y, fmaf(w2, av.z, fmaf(w3, bv.x, bs))));
    o.z = fmaf(w0, av.y, fmaf(w1, av.z, fmaf(w2, av.w, fmaf(w3, bv.y, bs))));
    o.w = fmaf(w0, av.z, fmaf(w1, av.w, fmaf(w2, ap4,  fmaf(w3, bv.z, bs))));

    __stcs((float4*)(out + (size_t)bc * HWSZ) + tid, o);
}

// ---------------------------------------------------------------------------
extern "C" void kernel_launch(void* const* d_in, const int* in_sizes, int n_in,
                              void* d_out, int out_size) {
    const float* x     = (const float*)d_in[0];
    const float* w1    = (const float*)d_in[1];
    const float* gamma = (const float*)d_in[2];
    const float* beta  = (const float*)d_in[3];
    const float* rmean = (const float*)d_in[4];
    const float* rvar  = (const float*)d_in[5];
    const float* w2    = (const float*)d_in[6];
    const float* b2    = (const float*)d_in[7];
    const float* bias  = (const float*)d_in[8];
    float* out = (float*)d_out;

    dim3 cgrid(HWSZ / 4 / 512, DIMC);
    for (int b = 0; b < BB; b++) {
        pool_wgen_kernel<<<POOL_BLOCKS, 256>>>(x, b, w1, gamma, beta,
                                               rmean, rvar, w2, b2);
        conv_kernel<<<cgrid, 512>>>(x, bias, out, b);
    }
}

// round 4
// speedup vs baseline: 1.1002x; 1.1002x over previous
#include <cuda_runtime.h>

#define DIMC 192
#define RJ   48          // DIM / RED
#define BB   4
#define HH   256
#define WW   256
#define HWSZ (HH * WW)   // 65536
#define EPSV 1e-5f

#define PSEGS 2                        // segments per plane in pool job
#define POOL_BLOCKS (DIMC * PSEGS)     // 384 pool blocks (512 threads each)
#define CONV_BLOCKS (DIMC * 32)        // 6144 conv blocks (512 threads each)

// Scratch (device globals; no allocation allowed).
__device__ float        g_part[DIMC * PSEGS];  // per-batch partials (batches serialize)
__device__ float        g_wt[BB * DIMC * 4];   // 4 surviving masked taps per (b,c)
__device__ unsigned int g_cnt = 0;             // wraps to 0 each batch (replay-safe)

// ---------------------------------------------------------------------------
// Pool job for batch pb: 384 blocks x 512 threads, each block reduces half a
// channel plane. Last finishing block runs the weight-gen MLP for batch pb.
// ---------------------------------------------------------------------------
__device__ __forceinline__ void pool_job(
        const float* __restrict__ x, int pb, int pblk,
        const float* __restrict__ w1,  const float* __restrict__ gamma,
        const float* __restrict__ beta, const float* __restrict__ rmean,
        const float* __restrict__ rvar, const float* __restrict__ w2,
        const float* __restrict__ b2) {
    const int c   = pblk >> 1;           // 0..191
    const int seg = pblk & 1;
    const int tid = threadIdx.x;

    // 32768 floats = 8192 float4 per block, 512 threads -> 16 iters.
    const float4* p = (const float4*)(x + ((size_t)(pb * DIMC + c)) * HWSZ)
                      + seg * (HWSZ / 4 / PSEGS);
    float s = 0.f;
    #pragma unroll
    for (int i = 0; i < HWSZ / 4 / PSEGS / 512; i++) {
        float4 v = p[tid + i * 512];
        s += (v.x + v.y) + (v.z + v.w);
    }
    #pragma unroll
    for (int o = 16; o > 0; o >>= 1) s += __shfl_down_sync(0xffffffffu, s, o);
    __shared__ float sm[16];
    const int lane = tid & 31, wrp = tid >> 5;
    if (lane == 0) sm[wrp] = s;
    __syncthreads();
    __shared__ bool is_last;
    if (tid == 0) {
        float t = 0.f;
        #pragma unroll
        for (int i = 0; i < 16; i++) t += sm[i];
        g_part[c * PSEGS + seg] = t;
        __threadfence();
        unsigned int old = atomicInc(&g_cnt, POOL_BLOCKS - 1);   // wraps 383 -> 0
        is_last = (old == POOL_BLOCKS - 1);
    }
    __syncthreads();
    if (!is_last) return;

    // ---- weight-gen tail for batch pb (one block) ----
    __shared__ float pooled[DIMC];
    __shared__ float t48[RJ];
    if (tid < DIMC) {
        const float* gp = g_part + tid * PSEGS;
        pooled[tid] = (gp[0] + gp[1]) * (1.0f / (float)HWSZ);
    }
    __syncthreads();
    if (tid < RJ) {
        const float* pw = w1 + tid * DIMC;
        float acc = 0.f;
        #pragma unroll 8
        for (int cc = 0; cc < DIMC; cc++) acc = fmaf(pooled[cc], pw[cc], acc);
        acc = gamma[tid] * (acc - rmean[tid]) * rsqrtf(rvar[tid] + EPSV) + beta[tid];
        t48[tid] = fmaxf(acc, 0.f);
    }
    __syncthreads();
    // 768 masked taps (mask 'A' keeps 3x3 positions 0..3): 512 threads, <=2 each.
    for (int idx = tid; idx < DIMC * 4; idx += 512) {
        const int cc = idx >> 2;
        const int k  = idx & 3;
        const int o  = cc * 9 + k;
        const float* pw2 = w2 + (size_t)o * RJ;
        float acc = b2[o];
        #pragma unroll
        for (int j = 0; j < RJ; j++) acc = fmaf(t48[j], pw2[j], acc);
        g_wt[(pb * DIMC + cc) * 4 + k] = acc;
    }
}

// ---------------------------------------------------------------------------
// Conv job for batch cb: 6144 blocks x 512 threads. Active taps:
//   out(y,x) = w0*in(y-1,x-1) + w1*in(y-1,x) + w2*in(y-1,x+1) + w3*in(y,x-1) + bias
// Reads via __ldcs (L2-resident from prior pool; evict after use), writes via
// __stcs (streaming). Halos via warp shuffles + rare seam fix-ups.
// ---------------------------------------------------------------------------
__device__ __forceinline__ void conv_job(
        const float* __restrict__ x, const float* __restrict__ bias,
        float* __restrict__ out, int cb, int cblk) {
    const int c    = cblk >> 5;              // 0..191
    const int tile = cblk & 31;
    const int bc = cb * DIMC + c;
    const float4 wv = *(const float4*)(g_wt + bc * 4);
    const float w0 = wv.x, w1 = wv.y, w2 = wv.z, w3 = wv.w;
    const float bs = bias[c];

    const int tid = tile * 512 + threadIdx.x;     // 0 .. HW/4-1
    const int xq = tid & 63;
    const int y  = tid >> 6;
    const int x0 = xq << 2;
    const int lane = threadIdx.x & 31;

    const float* base = x + (size_t)bc * HWSZ;
    const float* rowc = base + y * WW;
    const float* rowm = rowc - WW;

    const float4 bv = __ldcs((const float4*)(rowc + x0));

    float4 av;
    if (y > 0) {                              // warp-uniform
        av = __ldcs((const float4*)(rowm + x0));
    } else {
        av = make_float4(0.f, 0.f, 0.f, 0.f);
    }

    float am1 = __shfl_up_sync(0xffffffffu, av.w, 1);
    float bm1 = __shfl_up_sync(0xffffffffu, bv.w, 1);
    float ap4 = __shfl_down_sync(0xffffffffu, av.x, 1);

    if (lane == 0) {
        if (x0 > 0) {
            bm1 = rowc[x0 - 1];
            am1 = (y > 0) ? rowm[x0 - 1] : 0.f;
        } else {
            am1 = 0.f; bm1 = 0.f;
        }
    }
    if (lane == 31) {
        if (x0 + 4 < WW) {
            ap4 = (y > 0) ? rowm[x0 + 4] : 0.f;
        } else {
            ap4 = 0.f;
        }
    }

    float4 o;
    o.x = fmaf(w0, am1,  fmaf(w1, av.x, fmaf(w2, av.y, fmaf(w3, bm1,  bs))));
    o.y = fmaf(w0, av.x, fmaf(w1, av.y, fmaf(w2, av.z, fmaf(w3, bv.x, bs))));
    o.z = fmaf(w0, av.y, fmaf(w1, av.z, fmaf(w2, av.w, fmaf(w3, bv.y, bs))));
    o.w = fmaf(w0, av.z, fmaf(w1, av.w, fmaf(w2, ap4,  fmaf(w3, bv.z, bs))));

    __stcs((float4*)(out + (size_t)bc * HWSZ) + tid, o);
}

// ---------------------------------------------------------------------------
// Kernels
// ---------------------------------------------------------------------------
__global__ __launch_bounds__(512) void pool_only_kernel(
        const float* __restrict__ x, int pb,
        const float* __restrict__ w1, const float* __restrict__ gamma,
        const float* __restrict__ beta, const float* __restrict__ rmean,
        const float* __restrict__ rvar, const float* __restrict__ w2,
        const float* __restrict__ b2) {
    pool_job(x, pb, blockIdx.x, w1, gamma, beta, rmean, rvar, w2, b2);
}

// Pool blocks first (low blockIdx.x) so the next kernel's dependency clears early.
__global__ __launch_bounds__(512) void fused_kernel(
        const float* __restrict__ x, const float* __restrict__ bias,
        float* __restrict__ out, int cb,
        const float* __restrict__ w1, const float* __restrict__ gamma,
        const float* __restrict__ beta, const float* __restrict__ rmean,
        const float* __restrict__ rvar, const float* __restrict__ w2,
        const float* __restrict__ b2) {
    if (blockIdx.x < POOL_BLOCKS) {
        pool_job(x, cb + 1, blockIdx.x, w1, gamma, beta, rmean, rvar, w2, b2);
    } else {
        conv_job(x, bias, out, cb, blockIdx.x - POOL_BLOCKS);
    }
}

__global__ __launch_bounds__(512) void conv_only_kernel(
        const float* __restrict__ x, const float* __restrict__ bias,
        float* __restrict__ out, int cb) {
    conv_job(x, bias, out, cb, blockIdx.x);
}

// ---------------------------------------------------------------------------
extern "C" void kernel_launch(void* const* d_in, const int* in_sizes, int n_in,
                              void* d_out, int out_size) {
    const float* x     = (const float*)d_in[0];
    const float* w1    = (const float*)d_in[1];
    const float* gamma = (const float*)d_in[2];
    const float* beta  = (const float*)d_in[3];
    const float* rmean = (const float*)d_in[4];
    const float* rvar  = (const float*)d_in[5];
    const float* w2    = (const float*)d_in[6];
    const float* b2    = (const float*)d_in[7];
    const float* bias  = (const float*)d_in[8];
    float* out = (float*)d_out;

    pool_only_kernel<<<POOL_BLOCKS, 512>>>(x, 0, w1, gamma, beta,
                                           rmean, rvar, w2, b2);
    for (int b = 0; b < BB - 1; b++) {
        fused_kernel<<<POOL_BLOCKS + CONV_BLOCKS, 512>>>(
            x, bias, out, b, w1, gamma, beta, rmean, rvar, w2, b2);
    }
    conv_only_kernel<<<CONV_BLOCKS, 512>>>(x, bias, out, BB - 1);
}